// round 8
// baseline (speedup 1.0000x reference)
#include <cuda_runtime.h>
#include <cstdint>

// ----------------------------------------------------------------------------
// HandGNNEncoder: 2-layer GCN on a fixed 21-node skeleton + mean pool, fused.
//
//   h1 = relu( (A x) W1 + b1 )            (A x sparse: 44 nnz, 2 feature cols)
//   out = sum_s c[s] * h1[s,:] @ W2 + b2  where c[s] = (1/21) sum_t A[t,s]
//
// Phase-3 matvec uses packed fma.rn.f32x2 (FFMA2): W2 columns live in regs as
// 32 pre-packed b64 pairs; q read from shared as ulonglong2 (LDS.128 gives
// aligned reg pairs for free).
// ----------------------------------------------------------------------------

#define R2 0.70710678118654752440f   // 1/sqrt(2)
#define R3 0.57735026918962576451f   // 1/sqrt(3)
#define T3 (1.0f/3.0f)
#define W23 (R2*R3)

static __device__ const int g_rowptr[22] = {
    0,1,3,5,7,9,11,13,15,17,20,22,24,26,29,31,33,35,38,40,42,44};
static __device__ const int g_cols[44] = {
    0,
    1,0,  2,1,  3,2,  4,3,
    5,0,  6,5,  7,6,  8,7,
    9,0,5,  10,9,  11,10,  12,11,
    13,0,9, 14,13, 15,14, 16,15,
    17,0,13,18,17, 19,18, 20,19};
static __device__ const float g_w[44] = {
    1.0f,
    0.5f,R2,  0.5f,0.5f,  0.5f,0.5f,  0.5f,0.5f,
    0.5f,R2,  0.5f,0.5f,  0.5f,0.5f,  0.5f,0.5f,
    T3,R3,W23, 0.5f,W23,  0.5f,0.5f,  0.5f,0.5f,
    T3,R3,T3,  0.5f,W23,  0.5f,0.5f,  0.5f,0.5f,
    T3,R3,T3,  0.5f,W23,  0.5f,0.5f,  0.5f,0.5f};

__constant__ float c_c[21] = {
    (1.0f + 2.0f*R2 + 3.0f*R3)/21.0f,
    1.0f/21.0f, 1.0f/21.0f, 1.0f/21.0f, 0.5f/21.0f,
    (1.0f + W23)/21.0f, 1.0f/21.0f, 1.0f/21.0f, 0.5f/21.0f,
    (2.0f/3.0f + W23)/21.0f, 1.0f/21.0f, 1.0f/21.0f, 0.5f/21.0f,
    (2.0f/3.0f + W23)/21.0f, 1.0f/21.0f, 1.0f/21.0f, 0.5f/21.0f,
    (1.0f/3.0f + W23)/21.0f, 1.0f/21.0f, 1.0f/21.0f, 0.5f/21.0f
};

#define NGRAPHS 32768
#define GPT     16              // graphs per tile
#define NTILES  (NGRAPHS/GPT)   // 2048
#define NBLOCKS 296             // exactly 2 per SM (148 SMs), no wave spill
#define XA_STRIDE 44            // padded row (176B, 16B-aligned for float4)

__device__ __forceinline__ void ffma2(unsigned long long& acc,
                                      unsigned long long a,
                                      unsigned long long b) {
    asm("fma.rn.f32x2 %0, %1, %2, %0;" : "+l"(acc) : "l"(a), "l"(b));
}
__device__ __forceinline__ unsigned long long packf2(float lo, float hi) {
    unsigned long long r;
    asm("mov.b64 %0, {%1,%2};" : "=l"(r) : "f"(lo), "f"(hi));
    return r;
}
__device__ __forceinline__ void unpackf2(unsigned long long v, float& lo, float& hi) {
    asm("mov.b64 {%0,%1}, %2;" : "=f"(lo), "=f"(hi) : "l"(v));
}

__global__ void __launch_bounds__(256, 2)
hand_gnn_kernel(const float* __restrict__ x,   // [G,21,2]
                const float* __restrict__ W1,  // [2,64]
                const float* __restrict__ b1,  // [64]
                const float* __restrict__ W2,  // [64,128]
                const float* __restrict__ b2,  // [128]
                float* __restrict__ out)       // [G,128]
{
    __shared__ float s_q[GPT * 64];          // phase1a: staged x; phase2/3: q
    __shared__ float s_xa[GPT * XA_STRIDE];  // aggregated coords (padded rows)

    const int t = threadIdx.x;

    // ---- phase-3 params: thread owns output feature f; W2 col as packed pairs
    const int f  = t & 127;
    const int gh = t >> 7;
    unsigned long long w2p[32];
#pragma unroll
    for (int d = 0; d < 32; ++d)
        w2p[d] = packf2(W2[(2*d) * 128 + f], W2[(2*d+1) * 128 + f]);
    const unsigned long long b2p = packf2(b2[f], 0.0f);

    // ---- phase-2 params: thread owns hidden channel d2
    const int d2 = t & 63;
    const float w10 = W1[d2];
    const float w11 = W1[64 + d2];
    const float b1d = b1[d2];

    for (int tile = blockIdx.x; tile < NTILES; tile += gridDim.x) {
        const int g0 = tile * GPT;

        // ---- phase 1a: stage raw x (coalesced) ----
        const float* xg = x + (size_t)g0 * 42;
        for (int i = t; i < GPT * 42; i += 256) s_q[i] = xg[i];
        __syncthreads();

        // ---- phase 1b: sparse aggregate  xa[g][s][k] = sum_u A[s,u] x[g][u][k]
        for (int i = t; i < GPT * 42; i += 256) {
            const int g = i / 42;
            const int j = i - g * 42;
            const int s = j >> 1;
            const int k = j & 1;
            float acc = 0.0f;
            const int e0 = g_rowptr[s], e1 = g_rowptr[s + 1];
            for (int e = e0; e < e1; ++e)
                acc = fmaf(g_w[e], s_q[g * 42 + (g_cols[e] << 1) + k], acc);
            s_xa[g * XA_STRIDE + j] = acc;
        }
        __syncthreads();

        // ---- phase 2: q[g][d] = sum_s c[s]*relu(xa0*W1[0,d]+xa1*W1[1,d]+b1[d])
#pragma unroll
        for (int it = 0; it < GPT / 4; ++it) {
            const int g = (t >> 6) + it * 4;          // warp-uniform graph id
            const float4* xa4 = (const float4*)&s_xa[g * XA_STRIDE];
            float acc = 0.0f;
#pragma unroll
            for (int i = 0; i < 10; ++i) {            // s = 2i, 2i+1
                const float4 a = xa4[i];              // broadcast LDS.128
                float v0 = fmaf(a.x, w10, fmaf(a.y, w11, b1d));
                v0 = fmaxf(v0, 0.0f);
                acc = fmaf(v0, c_c[2*i], acc);
                float v1 = fmaf(a.z, w10, fmaf(a.w, w11, b1d));
                v1 = fmaxf(v1, 0.0f);
                acc = fmaf(v1, c_c[2*i+1], acc);
            }
            const float2 al = *(const float2*)&s_xa[g * XA_STRIDE + 40]; // s=20
            float v = fmaf(al.x, w10, fmaf(al.y, w11, b1d));
            v = fmaxf(v, 0.0f);
            acc = fmaf(v, c_c[20], acc);
            s_q[g * 64 + d2] = acc;
        }
        __syncthreads();

        // ---- phase 3: out[g][f] = q[g,:] . W2[:,f] + b2[f]  (packed FFMA2) --
#pragma unroll
        for (int it = 0; it < GPT / 2; ++it) {
            const int g = gh + it * 2;                // warp-uniform graph id
            const ulonglong2* qv = (const ulonglong2*)&s_q[g * 64];
            unsigned long long acc0 = b2p, acc1 = 0ull;
#pragma unroll
            for (int i = 0; i < 16; ++i) {
                const ulonglong2 q2 = qv[i];          // broadcast LDS.128 = 2 pairs
                ffma2(acc0, q2.x, w2p[2*i]);
                ffma2(acc1, q2.y, w2p[2*i+1]);
            }
            float l0, h0, l1, h1;
            unpackf2(acc0, l0, h0);
            unpackf2(acc1, l1, h1);
            out[(size_t)(g0 + g) * 128 + f] = (l0 + h0) + (l1 + h1);
        }
        __syncthreads();   // protect s_q before next tile restages x
    }
}

extern "C" void kernel_launch(void* const* d_in, const int* in_sizes, int n_in,
                              void* d_out, int out_size)
{
    const float* x  = (const float*)d_in[0];  // hand_landmarks [64,512,21,2]
    const float* W1 = (const float*)d_in[1];  // [2,64]
    const float* b1 = (const float*)d_in[2];  // [64]
    const float* W2 = (const float*)d_in[3];  // [64,128]
    const float* b2 = (const float*)d_in[4];  // [128]
    float* out = (float*)d_out;               // [64,512,128]

    hand_gnn_kernel<<<NBLOCKS, 256>>>(x, W1, b1, W2, b2, out);
}